// round 16
// baseline (speedup 1.0000x reference)
#include <cuda_runtime.h>
#include <math.h>

#define NN 10000
#define NE 160000
#define NG 64
#define EMB 128
#define MD 32
#define HID 642
#define EIN 321
#define PLD 644
#define CAT 768
#define EPSF 1e-5f
#define WCHUNK 7744

// ---------------- scratch (static device memory; no allocations) ----------------
__device__ float g_cat[NN * CAT];
__device__ float g_Pa[NN * PLD];
__device__ float g_Pb[NN * PLD];
__device__ float g_Ah[NN * EMB];
__device__ float g_Al[NN * EMB];
__device__ float g_Wh[256 * HID];
__device__ float g_Wl[256 * HID];
__device__ float g_We[11 * WCHUNK];
__device__ float g_seg[NN * MD];
__device__ float g_cnt[NN];
__device__ int g_cnti[NN];
__device__ int g_pos[NN];
__device__ int g_offb[NN];
__device__ int g_es[NE];
__device__ int g_ed[NE];
__device__ float g_z[NN * 160];
__device__ float g_h1[NN * 256];
__device__ float g_h2[NN * 128];
__device__ float g_f1[NN * 256];
__device__ float g_f2[NN * 256];
__device__ float g_f3[NN * 256];
__device__ float g_pool[NG * 256];
__device__ float g_pcnt[NG];

__device__ __forceinline__ float silu_f(float x) {
    return x * __fdividef(1.f, 1.f + __expf(-x));
}

__device__ __forceinline__ float to_tf32(float x) {
    unsigned u;
    asm("cvt.rna.tf32.f32 %0, %1;" : "=r"(u) : "f"(x));
    return __uint_as_float(u);
}

__device__ __forceinline__ void mma_tf32(float* c, unsigned a0, unsigned a1, unsigned a2, unsigned a3,
                                         unsigned b0, unsigned b1) {
    asm volatile(
        "mma.sync.aligned.m16n8k8.row.col.f32.tf32.tf32.f32 "
        "{%0,%1,%2,%3},{%4,%5,%6,%7},{%8,%9},{%0,%1,%2,%3};"
        : "+f"(c[0]), "+f"(c[1]), "+f"(c[2]), "+f"(c[3])
        : "r"(a0), "r"(a1), "r"(a2), "r"(a3), "r"(b0), "r"(b1));
}

// ---------------- small kernels ----------------
__global__ void k_zero_start() {
    int i = blockIdx.x * 256 + threadIdx.x;
    if (i < NN) { g_cnt[i] = 0.f; g_cnti[i] = 0; g_pos[i] = 0; }
    if (i < NG * 256) g_pool[i] = 0.f;
    if (i < NG) g_pcnt[i] = 0.f;
    if (i < NN * MD) g_seg[i] = 0.f;
}
__global__ void k_hist(const int* __restrict__ eidx) {
    int e = blockIdx.x * 256 + threadIdx.x;
    if (e < NE) atomicAdd(&g_cnti[eidx[NE + e]], 1);
}
// single-block exclusive scan of g_cnti -> g_offb; also fills g_cnt (float counts)
__global__ void k_scan() {
    __shared__ int tsum[256];
    int t = threadIdx.x;
    const int CH = (NN + 255) / 256;  // 40
    int base = t * CH;
    int s = 0;
    for (int i = 0; i < CH; i++) {
        int idx = base + i;
        if (idx < NN) s += g_cnti[idx];
    }
    tsum[t] = s;
    __syncthreads();
    if (t == 0) {
        int acc = 0;
        for (int i = 0; i < 256; i++) { int v = tsum[i]; tsum[i] = acc; acc += v; }
    }
    __syncthreads();
    int acc = tsum[t];
    for (int i = 0; i < CH; i++) {
        int idx = base + i;
        if (idx < NN) {
            g_offb[idx] = acc;
            int c = g_cnti[idx];
            g_cnt[idx] = (float)c;
            acc += c;
        }
    }
}
__global__ void k_scatter(const int* __restrict__ eidx) {
    int e = blockIdx.x * 256 + threadIdx.x;
    if (e < NE) {
        int s = eidx[e], d = eidx[NE + e];
        int p = g_offb[d] + atomicAdd(&g_pos[d], 1);
        g_es[p] = s;
        g_ed[p] = d;
    }
}
__global__ void k_embed(const int* __restrict__ atomids, const float* __restrict__ emb_w) {
    int i = blockIdx.x * 256 + threadIdx.x;
    if (i < NN * EMB) {
        int n = i >> 7, c = i & 127;
        float v = emb_w[atomids[n] * EMB + c];
        g_cat[n * CAT + c] = v;
        float h = to_tf32(v);
        g_Ah[i] = h;
        g_Al[i] = to_tf32(v - h);
    }
}
__global__ void k_split_w(const float* __restrict__ W1) {
    int i = blockIdx.x * 256 + threadIdx.x;
    if (i < 256 * HID) {
        float v = W1[i];
        float h = to_tf32(v);
        g_Wh[i] = h;
        g_Wl[i] = to_tf32(v - h);
    }
}
__global__ void k_prep_we(const float* __restrict__ W1, const float* __restrict__ W2) {
    int i = blockIdx.x * 256 + threadIdx.x;
    if (i >= 11 * WCHUNK) return;
    int c = i / WCHUNK, r = i % WCHUNK;
    float v = 0.f;
    if (r < 72 * 72) {
        int k = r / 72, f = r % 72;
        if (f < 64) {
            int n = ((f & 7) << 3) + (f >> 3);
            int gj = (c << 6) + n;
            if (k < 65 && gj < HID) v = to_tf32(W1[(256 + k) * HID + gj]);
        }
    } else {
        int r2 = r - 72 * 72;
        int j = r2 / 40, f = r2 % 40;
        if (f < 32) {
            int n = ((f & 3) << 3) + (f >> 2);
            int gj = (c << 6) + j;
            if (gj < HID) v = to_tf32(W2[gj * MD + n]);
        }
    }
    g_We[i] = v;
}
__global__ void k_pool(const int* __restrict__ batch) {
    int i = blockIdx.x * 256 + threadIdx.x;
    if (i < NN * 256) {
        int n = i >> 8, c = i & 255;
        atomicAdd(&g_pool[batch[n] * 256 + c], g_f3[i]);
    }
    if (i < NN) atomicAdd(&g_pcnt[batch[i]], 1.f);
}

// ---------------- pre-split 3xTF32 GEMM for Pa & Pb ----------------
__global__ __launch_bounds__(256) void k_gemm3p(
    const float* __restrict__ Ah, const float* __restrict__ Al,
    const float* __restrict__ Wh, const float* __restrict__ Wl,
    float* __restrict__ Ca, float* __restrict__ Cb) {
    __shared__ __align__(16) float sAh[128 * 20], sAl[128 * 20];
    __shared__ __align__(16) float sBh[16 * 72], sBl[16 * 72];
    int tid = threadIdx.x;
    int wid = tid >> 5, lane = tid & 31;
    int g = lane >> 2, tig = lane & 3;
    int r0 = wid << 4;
    int bm = blockIdx.y << 7;
    int half = (blockIdx.x >= 11) ? 1 : 0;
    int bn = (blockIdx.x - (half ? 11 : 0)) << 6;
    const float* Bh = Wh + (half ? (size_t)128 * HID : 0);
    const float* Bl = Wl + (half ? (size_t)128 * HID : 0);
    float* C = half ? Cb : Ca;

    float acc[8][4];
#pragma unroll
    for (int t = 0; t < 8; t++)
#pragma unroll
        for (int u = 0; u < 4; u++) acc[t][u] = 0.f;

    int ar = tid >> 1, ac0 = (tid & 1) << 3;
    bool aok = (bm + ar) < NN;
    const float* aph = Ah + (size_t)(bm + ar) * EMB + ac0;
    const float* apl = Al + (size_t)(bm + ar) * EMB + ac0;
    float* sph = &sAh[ar * 20 + ac0];
    float* spl = &sAl[ar * 20 + ac0];
    int bkr = tid >> 6;
    int bnc = tid & 63;
    int bgc = bn + bnc;
    bool bok = bgc < HID;
    const float* bph = Bh + (size_t)bkr * HID + bgc;
    const float* bpl = Bl + (size_t)bkr * HID + bgc;
    int bfi = bkr * 72 + ((bnc & 7) << 3) + (bnc >> 3);
    int arow_lo = (r0 + g) * 20, arow_hi = (r0 + g + 8) * 20;
    int bcol = g << 3;

    float4 vh0 = make_float4(0.f, 0.f, 0.f, 0.f), vh1 = vh0, vl0 = vh0, vl1 = vh0;
    float vbh[4], vbl[4];
    if (aok) {
        vh0 = *(const float4*)aph; vh1 = *(const float4*)(aph + 4);
        vl0 = *(const float4*)apl; vl1 = *(const float4*)(apl + 4);
    }
    aph += 16; apl += 16;
    {
        const float* ph = bph; const float* pl = bpl;
#pragma unroll
        for (int s = 0; s < 4; s++) {
            vbh[s] = bok ? ph[0] : 0.f;
            vbl[s] = bok ? pl[0] : 0.f;
            ph += 4 * HID; pl += 4 * HID;
        }
        bph += (size_t)16 * HID; bpl += (size_t)16 * HID;
    }

    for (int k0 = 0; k0 < 128; k0 += 16) {
        __syncthreads();
        *(float4*)sph = vh0; *(float4*)(sph + 4) = vh1;
        *(float4*)spl = vl0; *(float4*)(spl + 4) = vl1;
        {
            int fi = bfi;
#pragma unroll
            for (int s = 0; s < 4; s++) { sBh[fi] = vbh[s]; sBl[fi] = vbl[s]; fi += 288; }
        }
        if (k0 + 16 < 128) {
            if (aok) {
                vh0 = *(const float4*)aph; vh1 = *(const float4*)(aph + 4);
                vl0 = *(const float4*)apl; vl1 = *(const float4*)(apl + 4);
            }
            aph += 16; apl += 16;
            const float* ph = bph; const float* pl = bpl;
#pragma unroll
            for (int s = 0; s < 4; s++) {
                vbh[s] = bok ? ph[0] : 0.f;
                vbl[s] = bok ? pl[0] : 0.f;
                ph += 4 * HID; pl += 4 * HID;
            }
            bph += (size_t)16 * HID; bpl += (size_t)16 * HID;
        }
        __syncthreads();
#pragma unroll
        for (int ks = 0; ks < 2; ks++) {
            int kk = ks << 3;
            unsigned ah0 = __float_as_uint(sAh[arow_lo + kk + tig]);
            unsigned ah1 = __float_as_uint(sAh[arow_hi + kk + tig]);
            unsigned ah2 = __float_as_uint(sAh[arow_lo + kk + tig + 4]);
            unsigned ah3 = __float_as_uint(sAh[arow_hi + kk + tig + 4]);
            unsigned al0 = __float_as_uint(sAl[arow_lo + kk + tig]);
            unsigned al1 = __float_as_uint(sAl[arow_hi + kk + tig]);
            unsigned al2 = __float_as_uint(sAl[arow_lo + kk + tig + 4]);
            unsigned al3 = __float_as_uint(sAl[arow_hi + kk + tig + 4]);
            int bi0 = (kk + tig) * 72 + bcol;
            int bi1 = (kk + tig + 4) * 72 + bcol;
#pragma unroll
            for (int hlf = 0; hlf < 2; hlf++) {
                float bh0[4], bh1[4], bl0[4], bl1[4];
                *(float4*)bh0 = *(const float4*)&sBh[bi0 + (hlf << 2)];
                *(float4*)bh1 = *(const float4*)&sBh[bi1 + (hlf << 2)];
                *(float4*)bl0 = *(const float4*)&sBl[bi0 + (hlf << 2)];
                *(float4*)bl1 = *(const float4*)&sBl[bi1 + (hlf << 2)];
#pragma unroll
                for (int tt = 0; tt < 4; tt++) {
                    int t = (hlf << 2) + tt;
                    mma_tf32(acc[t], ah0, ah1, ah2, ah3,
                             __float_as_uint(bh0[tt]), __float_as_uint(bh1[tt]));
                    mma_tf32(acc[t], ah0, ah1, ah2, ah3,
                             __float_as_uint(bl0[tt]), __float_as_uint(bl1[tt]));
                    mma_tf32(acc[t], al0, al1, al2, al3,
                             __float_as_uint(bh0[tt]), __float_as_uint(bh1[tt]));
                }
            }
        }
    }

    int row0 = bm + r0 + g, row1 = row0 + 8;
#pragma unroll
    for (int t = 0; t < 8; t++) {
        int col = bn + (t << 3) + (tig << 1);
        if (col >= HID) continue;
        if (row0 < NN) *(float2*)&C[(size_t)row0 * PLD + col] = make_float2(acc[t][0], acc[t][1]);
        if (row1 < NN) *(float2*)&C[(size_t)row1 * PLD + col] = make_float2(acc[t][2], acc[t][3]);
    }
}

// ---------------- generic 3xTF32 GEMM ----------------
__global__ __launch_bounds__(256) void k_gemm3t(
    const float* __restrict__ A, const float* __restrict__ B,
    const float* __restrict__ bias, float* __restrict__ C,
    int M, int N, int K, int lda, int ldb, int ldc, int act, int inact) {
    __shared__ __align__(16) float sAh[128 * 20], sAl[128 * 20];
    __shared__ __align__(16) float sBh[16 * 72], sBl[16 * 72];
    int tid = threadIdx.x;
    int wid = tid >> 5, lane = tid & 31;
    int g = lane >> 2, tig = lane & 3;
    int r0 = wid << 4;
    int bm = blockIdx.y << 7, bn = blockIdx.x << 6;

    float acc[8][4];
#pragma unroll
    for (int t = 0; t < 8; t++)
#pragma unroll
        for (int u = 0; u < 4; u++) acc[t][u] = 0.f;

    int ar = tid >> 1, ac0 = (tid & 1) << 3;
    bool aok = (bm + ar) < M;
    const float* aptr = A + (size_t)(bm + ar) * lda + ac0;
    float* sph = &sAh[ar * 20 + ac0];
    float* spl = &sAl[ar * 20 + ac0];
    int bkr = tid >> 6;
    int bnc = tid & 63;
    int bgc = bn + bnc;
    bool bok = bgc < N;
    const float* bptr = B + (size_t)bkr * ldb + bgc;
    int bfi = bkr * 72 + ((bnc & 7) << 3) + (bnc >> 3);
    int arow_lo = (r0 + g) * 20, arow_hi = (r0 + g + 8) * 20;
    int bcol = g << 3;

    float va[8], vb[4];
#pragma unroll
    for (int j = 0; j < 8; j++) va[j] = 0.f;
    if (aok) {
        float4 t0 = *(const float4*)aptr;
        float4 t1 = *(const float4*)(aptr + 4);
        va[0] = t0.x; va[1] = t0.y; va[2] = t0.z; va[3] = t0.w;
        va[4] = t1.x; va[5] = t1.y; va[6] = t1.z; va[7] = t1.w;
    }
    aptr += 16;
    {
        const float* bp = bptr;
#pragma unroll
        for (int s = 0; s < 4; s++) { vb[s] = bok ? bp[0] : 0.f; bp += (size_t)4 * ldb; }
        bptr += (size_t)16 * ldb;
    }

    for (int k0 = 0; k0 < K; k0 += 16) {
        __syncthreads();
        {
#pragma unroll
            for (int j = 0; j < 8; j++) {
                float w = inact ? silu_f(va[j]) : va[j];
                float h = to_tf32(w);
                sph[j] = h;
                spl[j] = to_tf32(w - h);
            }
            int fi = bfi;
#pragma unroll
            for (int s = 0; s < 4; s++) {
                float h = to_tf32(vb[s]);
                sBh[fi] = h;
                sBl[fi] = to_tf32(vb[s] - h);
                fi += 288;
            }
        }
        if (k0 + 16 < K) {
#pragma unroll
            for (int j = 0; j < 8; j++) va[j] = 0.f;
            if (aok) {
                float4 t0 = *(const float4*)aptr;
                float4 t1 = *(const float4*)(aptr + 4);
                va[0] = t0.x; va[1] = t0.y; va[2] = t0.z; va[3] = t0.w;
                va[4] = t1.x; va[5] = t1.y; va[6] = t1.z; va[7] = t1.w;
            }
            aptr += 16;
            const float* bp = bptr;
#pragma unroll
            for (int s = 0; s < 4; s++) { vb[s] = bok ? bp[0] : 0.f; bp += (size_t)4 * ldb; }
            bptr += (size_t)16 * ldb;
        }
        __syncthreads();
#pragma unroll
        for (int ks = 0; ks < 2; ks++) {
            int kk = ks << 3;
            unsigned ah0 = __float_as_uint(sAh[arow_lo + kk + tig]);
            unsigned ah1 = __float_as_uint(sAh[arow_hi + kk + tig]);
            unsigned ah2 = __float_as_uint(sAh[arow_lo + kk + tig + 4]);
            unsigned ah3 = __float_as_uint(sAh[arow_hi + kk + tig + 4]);
            unsigned al0 = __float_as_uint(sAl[arow_lo + kk + tig]);
            unsigned al1 = __float_as_uint(sAl[arow_hi + kk + tig]);
            unsigned al2 = __float_as_uint(sAl[arow_lo + kk + tig + 4]);
            unsigned al3 = __float_as_uint(sAl[arow_hi + kk + tig + 4]);
            int bi0 = (kk + tig) * 72 + bcol;
            int bi1 = (kk + tig + 4) * 72 + bcol;
#pragma unroll
            for (int hlf = 0; hlf < 2; hlf++) {
                float bh0[4], bh1[4], bl0[4], bl1[4];
                *(float4*)bh0 = *(const float4*)&sBh[bi0 + (hlf << 2)];
                *(float4*)bh1 = *(const float4*)&sBh[bi1 + (hlf << 2)];
                *(float4*)bl0 = *(const float4*)&sBl[bi0 + (hlf << 2)];
                *(float4*)bl1 = *(const float4*)&sBl[bi1 + (hlf << 2)];
#pragma unroll
                for (int tt = 0; tt < 4; tt++) {
                    int t = (hlf << 2) + tt;
                    mma_tf32(acc[t], ah0, ah1, ah2, ah3,
                             __float_as_uint(bh0[tt]), __float_as_uint(bh1[tt]));
                    mma_tf32(acc[t], ah0, ah1, ah2, ah3,
                             __float_as_uint(bl0[tt]), __float_as_uint(bl1[tt]));
                    mma_tf32(acc[t], al0, al1, al2, al3,
                             __float_as_uint(bh0[tt]), __float_as_uint(bh1[tt]));
                }
            }
        }
    }

    int row0 = bm + r0 + g, row1 = row0 + 8;
#pragma unroll
    for (int t = 0; t < 8; t++) {
        int col = bn + (t << 3) + (tig << 1);
        if (col >= N) continue;
        float b0v = bias ? bias[col] : 0.f;
        float b1v = bias ? bias[col + 1] : 0.f;
        float v00 = acc[t][0] + b0v, v01 = acc[t][1] + b1v;
        float v10 = acc[t][2] + b0v, v11 = acc[t][3] + b1v;
        if (act) { v00 = silu_f(v00); v01 = silu_f(v01); v10 = silu_f(v10); v11 = silu_f(v11); }
        if (row0 < M) *(float2*)&C[(size_t)row0 * ldc + col] = make_float2(v00, v01);
        if (row1 < M) *(float2*)&C[(size_t)row1 * ldc + col] = make_float2(v10, v11);
    }
}

// ---------------- fused edge kernel v9: dst-sorted edges + double-buffered cp.async weights ----------------
__global__ __launch_bounds__(256, 2) void k_edge2(
    const float* __restrict__ coords,
    const float* __restrict__ b1,
    const float* __restrict__ b2,
    const float* __restrict__ eng, const float* __restrict__ enb) {
    extern __shared__ __align__(16) float sm[];
    float* s_fe = sm;
    float* s_H = sm;
    float* s_W0 = sm + 128 * 76;
    float* s_W1b = s_W0 + WCHUNK;
    float* s_b1 = s_W1b + WCHUNK;
    float* s_d2 = s_b1 + 648;
    int* s_src = (int*)(s_d2 + 128);
    int* s_dst = s_src + 128;

    int tid = threadIdx.x;
    int e0 = blockIdx.x << 7;

    unsigned w_smem0 = (unsigned)__cvta_generic_to_shared(s_W0);
    unsigned w_smem1 = (unsigned)__cvta_generic_to_shared(s_W1b);

    for (int idx = tid; idx < WCHUNK / 4; idx += 256) {
        asm volatile("cp.async.cg.shared.global [%0], [%1], 16;"
                     :: "r"(w_smem0 + (idx << 4)), "l"(g_We + (idx << 2)));
    }
    asm volatile("cp.async.commit_group;");

    if (tid < 128) {
        int e = e0 + tid;
        int s = g_es[e], d = g_ed[e];
        s_src[tid] = s; s_dst[tid] = d;
        float dx = coords[3 * s + 0] - coords[3 * d + 0];
        float dy = coords[3 * s + 1] - coords[3 * d + 1];
        float dz = coords[3 * s + 2] - coords[3 * d + 2];
        float d2 = dx * dx + dy * dy + dz * dz;
        s_d2[tid] = d2;
        s_fe[tid * 76 + 64] = to_tf32(d2);
#pragma unroll
        for (int j = 65; j < 72; j++) s_fe[tid * 76 + j] = 0.f;
    }
    for (int i = tid; i < 648; i += 256) s_b1[i] = (i < HID) ? b1[i] : 0.f;
    __syncthreads();
    for (int idx = tid; idx < 128 * 32; idx += 256) {
        int e = idx >> 5, i = idx & 31;
        float xs = s_d2[e] * __int_as_float((127 - i) << 23);
        float sv, cv;
        __sincosf(xs, &sv, &cv);
        s_fe[e * 76 + i] = to_tf32(sv);
        s_fe[e * 76 + 32 + i] = to_tf32(cv);
    }
    __syncthreads();

    int wid = tid >> 5, lane = tid & 31;
    int g = lane >> 2, tig = lane & 3;
    int r0 = wid << 4;
    int rlo = r0 + g, rhi = r0 + g + 8;

    unsigned feA[9][4];
#pragma unroll
    for (int ks = 0; ks < 9; ks++) {
        int k0 = ks << 3;
        feA[ks][0] = __float_as_uint(s_fe[rlo * 76 + k0 + tig]);
        feA[ks][1] = __float_as_uint(s_fe[rhi * 76 + k0 + tig]);
        feA[ks][2] = __float_as_uint(s_fe[rlo * 76 + k0 + tig + 4]);
        feA[ks][3] = __float_as_uint(s_fe[rhi * 76 + k0 + tig + 4]);
    }

    float acc[4][4];
#pragma unroll
    for (int t = 0; t < 4; t++)
#pragma unroll
        for (int u = 0; u < 4; u++) acc[t][u] = 0.f;

    for (int c = 0; c < 11; c++) {
        __syncthreads();

        if (c < 10) {
            unsigned dst = ((c + 1) & 1) ? w_smem1 : w_smem0;
            const float* wsrc = g_We + (c + 1) * WCHUNK;
            for (int idx = tid; idx < WCHUNK / 4; idx += 256) {
                asm volatile("cp.async.cg.shared.global [%0], [%1], 16;"
                             :: "r"(dst + (idx << 4)), "l"(wsrc + (idx << 2)));
            }
            asm volatile("cp.async.commit_group;");
        }

        int cb = c << 6;
        for (int it = tid; it < 128 * 16; it += 256) {
            int e = it >> 4, q = it & 15;
            int col = cb + (q << 2);
            float4 r = make_float4(0.f, 0.f, 0.f, 0.f);
            if (col < HID) {
                float4 pa = *(const float4*)&g_Pa[(size_t)s_dst[e] * PLD + col];
                float4 pb = *(const float4*)&g_Pb[(size_t)s_src[e] * PLD + col];
                r.x = pa.x + pb.x + s_b1[col];
                r.y = (col + 1 < HID) ? pa.y + pb.y + s_b1[col + 1] : 0.f;
                r.z = (col + 2 < HID) ? pa.z + pb.z + s_b1[col + 2] : 0.f;
                r.w = (col + 3 < HID) ? pa.w + pb.w + s_b1[col + 3] : 0.f;
            }
            *(float4*)&s_H[e * 68 + (q << 2)] = r;
        }
        if (c < 10) {
            asm volatile("cp.async.wait_group 1;" ::: "memory");
        } else {
            asm volatile("cp.async.wait_group 0;" ::: "memory");
        }
        __syncthreads();

        float* s_Wc1 = (c & 1) ? s_W1b : s_W0;
        float* s_Wc2 = s_Wc1 + 72 * 72;

        float c1[8][4];
#pragma unroll
        for (int t = 0; t < 8; t++)
#pragma unroll
            for (int u = 0; u < 4; u++) c1[t][u] = 0.f;
#pragma unroll
        for (int ks = 0; ks < 9; ks++) {
            int k0 = ks << 3;
            int bi0 = (k0 + tig) * 72 + (g << 3);
            int bi1 = (k0 + tig + 4) * 72 + (g << 3);
#pragma unroll
            for (int half = 0; half < 2; half++) {
                float w0[4], w1[4];
                *(float4*)w0 = *(const float4*)&s_Wc1[bi0 + (half << 2)];
                *(float4*)w1 = *(const float4*)&s_Wc1[bi1 + (half << 2)];
#pragma unroll
                for (int tt = 0; tt < 4; tt++) {
                    mma_tf32(c1[(half << 2) + tt], feA[ks][0], feA[ks][1], feA[ks][2], feA[ks][3],
                             __float_as_uint(w0[tt]), __float_as_uint(w1[tt]));
                }
            }
        }
#pragma unroll
        for (int t = 0; t < 8; t++) {
            int col = (t << 3) + (tig << 1);
            int i00 = rlo * 68 + col;
            int i10 = rhi * 68 + col;
            s_H[i00] = to_tf32(silu_f(c1[t][0] + s_H[i00]));
            s_H[i00 + 1] = to_tf32(silu_f(c1[t][1] + s_H[i00 + 1]));
            s_H[i10] = to_tf32(silu_f(c1[t][2] + s_H[i10]));
            s_H[i10 + 1] = to_tf32(silu_f(c1[t][3] + s_H[i10 + 1]));
        }
        __syncthreads();

#pragma unroll
        for (int ks = 0; ks < 8; ks++) {
            int k0 = ks << 3;
            unsigned a0 = __float_as_uint(s_H[rlo * 68 + k0 + tig]);
            unsigned a1 = __float_as_uint(s_H[rhi * 68 + k0 + tig]);
            unsigned a2 = __float_as_uint(s_H[rlo * 68 + k0 + tig + 4]);
            unsigned a3 = __float_as_uint(s_H[rhi * 68 + k0 + tig + 4]);
            float w0[4], w1[4];
            *(float4*)w0 = *(const float4*)&s_Wc2[(k0 + tig) * 40 + (g << 2)];
            *(float4*)w1 = *(const float4*)&s_Wc2[(k0 + tig + 4) * 40 + (g << 2)];
#pragma unroll
            for (int t = 0; t < 4; t++) {
                mma_tf32(acc[t], a0, a1, a2, a3,
                         __float_as_uint(w0[t]), __float_as_uint(w1[t]));
            }
        }
    }

    int dlo = s_dst[rlo], dhi = s_dst[rhi];
    float vlo[8], vhi[8];
    float Slo = 0.f, Shi = 0.f;
#pragma unroll
    for (int t = 0; t < 4; t++) {
        int col = (t << 3) + (tig << 1);
        float v0 = silu_f(acc[t][0] + b2[col]);
        float v1 = silu_f(acc[t][1] + b2[col + 1]);
        float v2 = silu_f(acc[t][2] + b2[col]);
        float v3 = silu_f(acc[t][3] + b2[col + 1]);
        vlo[t * 2] = v0; vlo[t * 2 + 1] = v1;
        vhi[t * 2] = v2; vhi[t * 2 + 1] = v3;
        Slo += v0 + v1; Shi += v2 + v3;
    }
    Slo += __shfl_xor_sync(0xffffffffu, Slo, 1);
    Slo += __shfl_xor_sync(0xffffffffu, Slo, 2);
    Shi += __shfl_xor_sync(0xffffffffu, Shi, 1);
    Shi += __shfl_xor_sync(0xffffffffu, Shi, 2);
    float mlo = Slo * (1.f / 32.f), mhi = Shi * (1.f / 32.f);
    float Vlo = 0.f, Vhi = 0.f;
#pragma unroll
    for (int u = 0; u < 8; u++) {
        float d0 = vlo[u] - mlo; Vlo += d0 * d0;
        float d1 = vhi[u] - mhi; Vhi += d1 * d1;
    }
    Vlo += __shfl_xor_sync(0xffffffffu, Vlo, 1);
    Vlo += __shfl_xor_sync(0xffffffffu, Vlo, 2);
    Vhi += __shfl_xor_sync(0xffffffffu, Vhi, 1);
    Vhi += __shfl_xor_sync(0xffffffffu, Vhi, 2);
    float ilo = rsqrtf(Vlo * (1.f / 32.f) + EPSF);
    float ihi = rsqrtf(Vhi * (1.f / 32.f) + EPSF);
#pragma unroll
    for (int t = 0; t < 4; t++) {
#pragma unroll
        for (int d = 0; d < 2; d++) {
            int col = (t << 3) + (tig << 1) + d;
            atomicAdd(&g_seg[dlo * MD + col], (vlo[t * 2 + d] - mlo) * ilo * eng[col] + enb[col]);
            atomicAdd(&g_seg[dhi * MD + col], (vhi[t * 2 + d] - mhi) * ihi * eng[col] + enb[col]);
        }
    }
}

// ---------------- node pre ----------------
__global__ void k_node_pre(int off, const float* __restrict__ eng, const float* __restrict__ enb,
                           const float* __restrict__ n1g, const float* __restrict__ n1b) {
    int node = blockIdx.x * 8 + (threadIdx.x >> 5);
    int lane = threadIdx.x & 31;
    if (node >= NN) return;

    float x = g_seg[node * MD + lane] / fmaxf(g_cnt[node], 1.f);
    g_seg[node * MD + lane] = 0.f;
    float S = x;
#pragma unroll
    for (int o = 16; o; o >>= 1) S += __shfl_xor_sync(0xffffffffu, S, o);
    float mean = S * (1.f / 32.f);
    float d = x - mean;
    float V = d * d;
#pragma unroll
    for (int o = 16; o; o >>= 1) V += __shfl_xor_sync(0xffffffffu, V, o);
    V *= (1.f / 32.f);
    g_z[node * 160 + 128 + lane] = d * rsqrtf(V + EPSF) * eng[lane] + enb[lane];

    float4 v = *(const float4*)&g_cat[node * CAT + off + lane * 4];
    S = v.x + v.y + v.z + v.w;
#pragma unroll
    for (int o = 16; o; o >>= 1) S += __shfl_xor_sync(0xffffffffu, S, o);
    mean = S * (1.f / 128.f);
    float dx = v.x - mean, dy = v.y - mean, dz = v.z - mean, dw = v.w - mean;
    V = dx * dx + dy * dy + dz * dz + dw * dw;
#pragma unroll
    for (int o = 16; o; o >>= 1) V += __shfl_xor_sync(0xffffffffu, V, o);
    V *= (1.f / 128.f);
    float inv = rsqrtf(V + EPSF);
    float4 g4 = *(const float4*)&n1g[lane * 4];
    float4 b4 = *(const float4*)&n1b[lane * 4];
    float4 o4;
    o4.x = dx * inv * g4.x + b4.x;
    o4.y = dy * inv * g4.y + b4.y;
    o4.z = dz * inv * g4.z + b4.z;
    o4.w = dw * inv * g4.w + b4.w;
    *(float4*)&g_z[node * 160 + lane * 4] = o4;
}

// ---------------- node post ----------------
__global__ void k_node_post(int off, const float* __restrict__ n2g, const float* __restrict__ n2b) {
    int node = blockIdx.x * 8 + (threadIdx.x >> 5);
    int lane = threadIdx.x & 31;
    if (node >= NN) return;
    float4 v = *(const float4*)&g_h2[node * 128 + lane * 4];
    float S = v.x + v.y + v.z + v.w;
#pragma unroll
    for (int o = 16; o; o >>= 1) S += __shfl_xor_sync(0xffffffffu, S, o);
    float mean = S * (1.f / 128.f);
    float dx = v.x - mean, dy = v.y - mean, dz = v.z - mean, dw = v.w - mean;
    float V = dx * dx + dy * dy + dz * dz + dw * dw;
#pragma unroll
    for (int o = 16; o; o >>= 1) V += __shfl_xor_sync(0xffffffffu, V, o);
    V *= (1.f / 128.f);
    float inv = rsqrtf(V + EPSF);
    float4 g4 = *(const float4*)&n2g[lane * 4];
    float4 b4 = *(const float4*)&n2b[lane * 4];
    float4 old = *(const float4*)&g_cat[node * CAT + off + lane * 4];
    float4 o4;
    o4.x = old.x + dx * inv * g4.x + b4.x;
    o4.y = old.y + dy * inv * g4.y + b4.y;
    o4.z = old.z + dz * inv * g4.z + b4.z;
    o4.w = old.w + dw * inv * g4.w + b4.w;
    *(float4*)&g_cat[node * CAT + off + 128 + lane * 4] = o4;
    int base = node * EMB + lane * 4;
    float h;
    h = to_tf32(o4.x); g_Ah[base + 0] = h; g_Al[base + 0] = to_tf32(o4.x - h);
    h = to_tf32(o4.y); g_Ah[base + 1] = h; g_Al[base + 1] = to_tf32(o4.y - h);
    h = to_tf32(o4.z); g_Ah[base + 2] = h; g_Al[base + 2] = to_tf32(o4.z - h);
    h = to_tf32(o4.w); g_Ah[base + 3] = h; g_Al[base + 3] = to_tf32(o4.w - h);
}

// ---------------- graph head ----------------
__global__ void k_graph(const float* __restrict__ g1W, const float* __restrict__ g1b,
                        const float* __restrict__ g2W, const float* __restrict__ g2b,
                        const float* __restrict__ g3W, const float* __restrict__ g3b,
                        float* __restrict__ out) {
    __shared__ float h[256], t[256];
    int g = blockIdx.x, tid = threadIdx.x;
    float c = fmaxf(g_pcnt[g], 1.f);
    h[tid] = g_pool[g * 256 + tid] / c;
    __syncthreads();
    float a = g1b[tid];
    for (int k = 0; k < 256; k++) a += h[k] * g1W[k * 256 + tid];
    t[tid] = silu_f(a);
    __syncthreads();
    h[tid] = t[tid];
    __syncthreads();
    a = g2b[tid];
    for (int k = 0; k < 256; k++) a += h[k] * g2W[k * 256 + tid];
    t[tid] = silu_f(a);
    __syncthreads();
    h[tid] = t[tid];
    __syncthreads();
    t[tid] = h[tid] * g3W[tid];
    __syncthreads();
    for (int s = 128; s; s >>= 1) {
        if (tid < s) t[tid] += t[tid + s];
        __syncthreads();
    }
    if (tid == 0) out[g] = t[0] + g3b[0];
}

// ---------------- launch ----------------
extern "C" void kernel_launch(void* const* d_in, const int* in_sizes, int n_in,
                              void* d_out, int out_size) {
    const int* atomids = (const int*)d_in[0];
    const float* coords = (const float*)d_in[1];
    const int* eidx = (const int*)d_in[2];
    const int* batch = (const int*)d_in[3];
    const float* emb_w = (const float*)d_in[4];
    const float* eW1 = (const float*)d_in[5];
    const float* eb1 = (const float*)d_in[6];
    const float* eW2 = (const float*)d_in[7];
    const float* eb2 = (const float*)d_in[8];
    const float* en_g = (const float*)d_in[9];
    const float* en_b = (const float*)d_in[10];
    const float* nn1_g = (const float*)d_in[11];
    const float* nn1_b = (const float*)d_in[12];
    const float* nW1 = (const float*)d_in[13];
    const float* nb1 = (const float*)d_in[14];
    const float* nW2 = (const float*)d_in[15];
    const float* nb2 = (const float*)d_in[16];
    const float* nn2_g = (const float*)d_in[17];
    const float* nn2_b = (const float*)d_in[18];
    const float* f1W = (const float*)d_in[19];
    const float* f1b = (const float*)d_in[20];
    const float* f2W = (const float*)d_in[21];
    const float* f2b = (const float*)d_in[22];
    const float* f3W = (const float*)d_in[23];
    const float* f3b = (const float*)d_in[24];
    const float* g1W = (const float*)d_in[25];
    const float* g1b = (const float*)d_in[26];
    const float* g2W = (const float*)d_in[27];
    const float* g2b = (const float*)d_in[28];
    const float* g3W = (const float*)d_in[29];
    const float* g3b = (const float*)d_in[30];
    float* out = (float*)d_out;

    const int smem_edge = (128 * 76 + 2 * WCHUNK + 648 + 128 + 256) * 4;  // 104992 B
    cudaFuncSetAttribute(k_edge2, cudaFuncAttributeMaxDynamicSharedMemorySize, smem_edge);

    float *pcat, *pPa, *pPb, *pAh, *pAl, *pWh, *pWl, *pz, *ph1, *ph2, *pf1, *pf2, *pf3;
    cudaGetSymbolAddress((void**)&pcat, g_cat);
    cudaGetSymbolAddress((void**)&pPa, g_Pa);
    cudaGetSymbolAddress((void**)&pPb, g_Pb);
    cudaGetSymbolAddress((void**)&pAh, g_Ah);
    cudaGetSymbolAddress((void**)&pAl, g_Al);
    cudaGetSymbolAddress((void**)&pWh, g_Wh);
    cudaGetSymbolAddress((void**)&pWl, g_Wl);
    cudaGetSymbolAddress((void**)&pz, g_z);
    cudaGetSymbolAddress((void**)&ph1, g_h1);
    cudaGetSymbolAddress((void**)&ph2, g_h2);
    cudaGetSymbolAddress((void**)&pf1, g_f1);
    cudaGetSymbolAddress((void**)&pf2, g_f2);
    cudaGetSymbolAddress((void**)&pf3, g_f3);

    // preprocessing (once): zero, dst-histogram, scan, dst-sorted edge permutation
    k_zero_start<<<(NN * MD + 255) / 256, 256>>>();
    k_hist<<<(NE + 255) / 256, 256>>>(eidx);
    k_scan<<<1, 256>>>();
    k_scatter<<<(NE + 255) / 256, 256>>>(eidx);
    k_embed<<<(NN * EMB + 255) / 256, 256>>>(atomids, emb_w);

    const int MB = (NN + 127) / 128;  // 79

    for (int k = 0; k < 5; k++) {
        int off = 128 * k;
        k_split_w<<<(256 * HID + 255) / 256, 256>>>(eW1 + (size_t)k * EIN * HID);
        k_prep_we<<<(11 * WCHUNK + 255) / 256, 256>>>(eW1 + (size_t)k * EIN * HID,
                                                      eW2 + (size_t)k * HID * MD);
        k_gemm3p<<<dim3(22, MB), 256>>>(pAh, pAl, pWh, pWl, pPa, pPb);
        k_edge2<<<NE / 128, 256, smem_edge>>>(coords, eb1 + k * HID, eb2 + k * MD,
                                              en_g + k * MD, en_b + k * MD);
        k_node_pre<<<NN / 8, 256>>>(off, en_g + k * MD, en_b + k * MD,
                                    nn1_g + k * EMB, nn1_b + k * EMB);
        k_gemm3t<<<dim3(4, MB), 256>>>(pz, nW1 + (size_t)k * 160 * 256, nb1 + k * 256, ph1,
                                       NN, 256, 160, 160, 256, 256, 1, 0);
        k_gemm3t<<<dim3(2, MB), 256>>>(ph1, nW2 + (size_t)k * 256 * 128, nb2 + k * 128, ph2,
                                       NN, 128, 256, 256, 128, 128, 0, 0);
        k_node_post<<<NN / 8, 256>>>(off, nn2_g + k * EMB, nn2_b + k * EMB);
    }

    k_gemm3t<<<dim3(4, MB), 256>>>(pcat, f1W, f1b, pf1, NN, 256, CAT, CAT, 256, 256, 1, 1);
    k_gemm3t<<<dim3(4, MB), 256>>>(pf1, f2W, f2b, pf2, NN, 256, 256, 256, 256, 256, 1, 0);
    k_gemm3t<<<dim3(4, MB), 256>>>(pf2, f3W, f3b, pf3, NN, 256, 256, 256, 256, 256, 1, 0);
    k_pool<<<(NN * 256 + 255) / 256, 256>>>(batch);
    k_graph<<<NG, 256>>>(g1W, g1b, g2W, g2b, g3W, g3b, out);
}

// round 17
// speedup vs baseline: 1.0164x; 1.0164x over previous
#include <cuda_runtime.h>
#include <math.h>

#define NN 10000
#define NE 160000
#define NG 64
#define EMB 128
#define MD 32
#define HID 642
#define EIN 321
#define PLD 644
#define CAT 768
#define EPSF 1e-5f
#define WCHUNK 7744

// ---------------- scratch (static device memory; no allocations) ----------------
__device__ float g_cat[NN * CAT];
__device__ float g_Pa[NN * PLD];
__device__ float g_Pb[NN * PLD];
__device__ float g_Ah[NN * EMB];
__device__ float g_Al[NN * EMB];
__device__ float g_Wh[256 * HID];
__device__ float g_Wl[256 * HID];
__device__ float g_We[11 * WCHUNK];
__device__ float g_seg[NN * MD];
__device__ float g_cnt[NN];
__device__ float g_z[NN * 160];
__device__ float g_h1[NN * 256];
__device__ float g_h2[NN * 128];
__device__ float g_f1[NN * 256];
__device__ float g_f2[NN * 256];
__device__ float g_f3[NN * 256];
__device__ float g_pool[NG * 256];
__device__ float g_pcnt[NG];

__device__ __forceinline__ float silu_f(float x) {
    return x * __fdividef(1.f, 1.f + __expf(-x));
}

__device__ __forceinline__ float to_tf32(float x) {
    unsigned u;
    asm("cvt.rna.tf32.f32 %0, %1;" : "=r"(u) : "f"(x));
    return __uint_as_float(u);
}

__device__ __forceinline__ void mma_tf32(float* c, unsigned a0, unsigned a1, unsigned a2, unsigned a3,
                                         unsigned b0, unsigned b1) {
    asm volatile(
        "mma.sync.aligned.m16n8k8.row.col.f32.tf32.tf32.f32 "
        "{%0,%1,%2,%3},{%4,%5,%6,%7},{%8,%9},{%0,%1,%2,%3};"
        : "+f"(c[0]), "+f"(c[1]), "+f"(c[2]), "+f"(c[3])
        : "r"(a0), "r"(a1), "r"(a2), "r"(a3), "r"(b0), "r"(b1));
}

// ---------------- small kernels ----------------
__global__ void k_zero_start() {
    int i = blockIdx.x * 256 + threadIdx.x;
    if (i < NN) g_cnt[i] = 0.f;
    if (i < NG * 256) g_pool[i] = 0.f;
    if (i < NG) g_pcnt[i] = 0.f;
    if (i < NN * MD) g_seg[i] = 0.f;
}
__global__ void k_deg(const int* __restrict__ eidx) {
    int e = blockIdx.x * 256 + threadIdx.x;
    if (e < NE) atomicAdd(&g_cnt[eidx[NE + e]], 1.f);
}
__global__ void k_embed(const int* __restrict__ atomids, const float* __restrict__ emb_w) {
    int i = blockIdx.x * 256 + threadIdx.x;
    if (i < NN * EMB) {
        int n = i >> 7, c = i & 127;
        float v = emb_w[atomids[n] * EMB + c];
        g_cat[n * CAT + c] = v;
        float h = to_tf32(v);
        g_Ah[i] = h;
        g_Al[i] = to_tf32(v - h);
    }
}
__global__ void k_split_w(const float* __restrict__ W1) {
    int i = blockIdx.x * 256 + threadIdx.x;
    if (i < 256 * HID) {
        float v = W1[i];
        float h = to_tf32(v);
        g_Wh[i] = h;
        g_Wl[i] = to_tf32(v - h);
    }
}
__global__ void k_prep_we(const float* __restrict__ W1, const float* __restrict__ W2) {
    int i = blockIdx.x * 256 + threadIdx.x;
    if (i >= 11 * WCHUNK) return;
    int c = i / WCHUNK, r = i % WCHUNK;
    float v = 0.f;
    if (r < 72 * 72) {
        int k = r / 72, f = r % 72;
        if (f < 64) {
            int n = ((f & 7) << 3) + (f >> 3);
            int gj = (c << 6) + n;
            if (k < 65 && gj < HID) v = to_tf32(W1[(256 + k) * HID + gj]);
        }
    } else {
        int r2 = r - 72 * 72;
        int j = r2 / 40, f = r2 % 40;
        if (f < 32) {
            int n = ((f & 3) << 3) + (f >> 2);
            int gj = (c << 6) + j;
            if (gj < HID) v = to_tf32(W2[gj * MD + n]);
        }
    }
    g_We[i] = v;
}
__global__ void k_pool(const int* __restrict__ batch) {
    int i = blockIdx.x * 256 + threadIdx.x;
    if (i < NN * 256) {
        int n = i >> 8, c = i & 255;
        atomicAdd(&g_pool[batch[n] * 256 + c], g_f3[i]);
    }
    if (i < NN) atomicAdd(&g_pcnt[batch[i]], 1.f);
}

// ---------------- pre-split 3xTF32 GEMM for Pa & Pb ----------------
__global__ __launch_bounds__(256) void k_gemm3p(
    const float* __restrict__ Ah, const float* __restrict__ Al,
    const float* __restrict__ Wh, const float* __restrict__ Wl,
    float* __restrict__ Ca, float* __restrict__ Cb) {
    __shared__ __align__(16) float sAh[128 * 20], sAl[128 * 20];
    __shared__ __align__(16) float sBh[16 * 72], sBl[16 * 72];
    int tid = threadIdx.x;
    int wid = tid >> 5, lane = tid & 31;
    int g = lane >> 2, tig = lane & 3;
    int r0 = wid << 4;
    int bm = blockIdx.y << 7;
    int half = (blockIdx.x >= 11) ? 1 : 0;
    int bn = (blockIdx.x - (half ? 11 : 0)) << 6;
    const float* Bh = Wh + (half ? (size_t)128 * HID : 0);
    const float* Bl = Wl + (half ? (size_t)128 * HID : 0);
    float* C = half ? Cb : Ca;

    float acc[8][4];
#pragma unroll
    for (int t = 0; t < 8; t++)
#pragma unroll
        for (int u = 0; u < 4; u++) acc[t][u] = 0.f;

    int ar = tid >> 1, ac0 = (tid & 1) << 3;
    bool aok = (bm + ar) < NN;
    const float* aph = Ah + (size_t)(bm + ar) * EMB + ac0;
    const float* apl = Al + (size_t)(bm + ar) * EMB + ac0;
    float* sph = &sAh[ar * 20 + ac0];
    float* spl = &sAl[ar * 20 + ac0];
    int bkr = tid >> 6;
    int bnc = tid & 63;
    int bgc = bn + bnc;
    bool bok = bgc < HID;
    const float* bph = Bh + (size_t)bkr * HID + bgc;
    const float* bpl = Bl + (size_t)bkr * HID + bgc;
    int bfi = bkr * 72 + ((bnc & 7) << 3) + (bnc >> 3);
    int arow_lo = (r0 + g) * 20, arow_hi = (r0 + g + 8) * 20;
    int bcol = g << 3;

    float4 vh0 = make_float4(0.f, 0.f, 0.f, 0.f), vh1 = vh0, vl0 = vh0, vl1 = vh0;
    float vbh[4], vbl[4];
    if (aok) {
        vh0 = *(const float4*)aph; vh1 = *(const float4*)(aph + 4);
        vl0 = *(const float4*)apl; vl1 = *(const float4*)(apl + 4);
    }
    aph += 16; apl += 16;
    {
        const float* ph = bph; const float* pl = bpl;
#pragma unroll
        for (int s = 0; s < 4; s++) {
            vbh[s] = bok ? ph[0] : 0.f;
            vbl[s] = bok ? pl[0] : 0.f;
            ph += 4 * HID; pl += 4 * HID;
        }
        bph += (size_t)16 * HID; bpl += (size_t)16 * HID;
    }

    for (int k0 = 0; k0 < 128; k0 += 16) {
        __syncthreads();
        *(float4*)sph = vh0; *(float4*)(sph + 4) = vh1;
        *(float4*)spl = vl0; *(float4*)(spl + 4) = vl1;
        {
            int fi = bfi;
#pragma unroll
            for (int s = 0; s < 4; s++) { sBh[fi] = vbh[s]; sBl[fi] = vbl[s]; fi += 288; }
        }
        if (k0 + 16 < 128) {
            if (aok) {
                vh0 = *(const float4*)aph; vh1 = *(const float4*)(aph + 4);
                vl0 = *(const float4*)apl; vl1 = *(const float4*)(apl + 4);
            }
            aph += 16; apl += 16;
            const float* ph = bph; const float* pl = bpl;
#pragma unroll
            for (int s = 0; s < 4; s++) {
                vbh[s] = bok ? ph[0] : 0.f;
                vbl[s] = bok ? pl[0] : 0.f;
                ph += 4 * HID; pl += 4 * HID;
            }
            bph += (size_t)16 * HID; bpl += (size_t)16 * HID;
        }
        __syncthreads();
#pragma unroll
        for (int ks = 0; ks < 2; ks++) {
            int kk = ks << 3;
            unsigned ah0 = __float_as_uint(sAh[arow_lo + kk + tig]);
            unsigned ah1 = __float_as_uint(sAh[arow_hi + kk + tig]);
            unsigned ah2 = __float_as_uint(sAh[arow_lo + kk + tig + 4]);
            unsigned ah3 = __float_as_uint(sAh[arow_hi + kk + tig + 4]);
            unsigned al0 = __float_as_uint(sAl[arow_lo + kk + tig]);
            unsigned al1 = __float_as_uint(sAl[arow_hi + kk + tig]);
            unsigned al2 = __float_as_uint(sAl[arow_lo + kk + tig + 4]);
            unsigned al3 = __float_as_uint(sAl[arow_hi + kk + tig + 4]);
            int bi0 = (kk + tig) * 72 + bcol;
            int bi1 = (kk + tig + 4) * 72 + bcol;
#pragma unroll
            for (int hlf = 0; hlf < 2; hlf++) {
                float bh0[4], bh1[4], bl0[4], bl1[4];
                *(float4*)bh0 = *(const float4*)&sBh[bi0 + (hlf << 2)];
                *(float4*)bh1 = *(const float4*)&sBh[bi1 + (hlf << 2)];
                *(float4*)bl0 = *(const float4*)&sBl[bi0 + (hlf << 2)];
                *(float4*)bl1 = *(const float4*)&sBl[bi1 + (hlf << 2)];
#pragma unroll
                for (int tt = 0; tt < 4; tt++) {
                    int t = (hlf << 2) + tt;
                    mma_tf32(acc[t], ah0, ah1, ah2, ah3,
                             __float_as_uint(bh0[tt]), __float_as_uint(bh1[tt]));
                    mma_tf32(acc[t], ah0, ah1, ah2, ah3,
                             __float_as_uint(bl0[tt]), __float_as_uint(bl1[tt]));
                    mma_tf32(acc[t], al0, al1, al2, al3,
                             __float_as_uint(bh0[tt]), __float_as_uint(bh1[tt]));
                }
            }
        }
    }

    int row0 = bm + r0 + g, row1 = row0 + 8;
#pragma unroll
    for (int t = 0; t < 8; t++) {
        int col = bn + (t << 3) + (tig << 1);
        if (col >= HID) continue;
        if (row0 < NN) *(float2*)&C[(size_t)row0 * PLD + col] = make_float2(acc[t][0], acc[t][1]);
        if (row1 < NN) *(float2*)&C[(size_t)row1 * PLD + col] = make_float2(acc[t][2], acc[t][3]);
    }
}

// ---------------- generic 3xTF32 GEMM ----------------
__global__ __launch_bounds__(256) void k_gemm3t(
    const float* __restrict__ A, const float* __restrict__ B,
    const float* __restrict__ bias, float* __restrict__ C,
    int M, int N, int K, int lda, int ldb, int ldc, int act, int inact) {
    __shared__ __align__(16) float sAh[128 * 20], sAl[128 * 20];
    __shared__ __align__(16) float sBh[16 * 72], sBl[16 * 72];
    int tid = threadIdx.x;
    int wid = tid >> 5, lane = tid & 31;
    int g = lane >> 2, tig = lane & 3;
    int r0 = wid << 4;
    int bm = blockIdx.y << 7, bn = blockIdx.x << 6;

    float acc[8][4];
#pragma unroll
    for (int t = 0; t < 8; t++)
#pragma unroll
        for (int u = 0; u < 4; u++) acc[t][u] = 0.f;

    int ar = tid >> 1, ac0 = (tid & 1) << 3;
    bool aok = (bm + ar) < M;
    const float* aptr = A + (size_t)(bm + ar) * lda + ac0;
    float* sph = &sAh[ar * 20 + ac0];
    float* spl = &sAl[ar * 20 + ac0];
    int bkr = tid >> 6;
    int bnc = tid & 63;
    int bgc = bn + bnc;
    bool bok = bgc < N;
    const float* bptr = B + (size_t)bkr * ldb + bgc;
    int bfi = bkr * 72 + ((bnc & 7) << 3) + (bnc >> 3);
    int arow_lo = (r0 + g) * 20, arow_hi = (r0 + g + 8) * 20;
    int bcol = g << 3;

    float va[8], vb[4];
#pragma unroll
    for (int j = 0; j < 8; j++) va[j] = 0.f;
    if (aok) {
        float4 t0 = *(const float4*)aptr;
        float4 t1 = *(const float4*)(aptr + 4);
        va[0] = t0.x; va[1] = t0.y; va[2] = t0.z; va[3] = t0.w;
        va[4] = t1.x; va[5] = t1.y; va[6] = t1.z; va[7] = t1.w;
    }
    aptr += 16;
    {
        const float* bp = bptr;
#pragma unroll
        for (int s = 0; s < 4; s++) { vb[s] = bok ? bp[0] : 0.f; bp += (size_t)4 * ldb; }
        bptr += (size_t)16 * ldb;
    }

    for (int k0 = 0; k0 < K; k0 += 16) {
        __syncthreads();
        {
#pragma unroll
            for (int j = 0; j < 8; j++) {
                float w = inact ? silu_f(va[j]) : va[j];
                float h = to_tf32(w);
                sph[j] = h;
                spl[j] = to_tf32(w - h);
            }
            int fi = bfi;
#pragma unroll
            for (int s = 0; s < 4; s++) {
                float h = to_tf32(vb[s]);
                sBh[fi] = h;
                sBl[fi] = to_tf32(vb[s] - h);
                fi += 288;
            }
        }
        if (k0 + 16 < K) {
#pragma unroll
            for (int j = 0; j < 8; j++) va[j] = 0.f;
            if (aok) {
                float4 t0 = *(const float4*)aptr;
                float4 t1 = *(const float4*)(aptr + 4);
                va[0] = t0.x; va[1] = t0.y; va[2] = t0.z; va[3] = t0.w;
                va[4] = t1.x; va[5] = t1.y; va[6] = t1.z; va[7] = t1.w;
            }
            aptr += 16;
            const float* bp = bptr;
#pragma unroll
            for (int s = 0; s < 4; s++) { vb[s] = bok ? bp[0] : 0.f; bp += (size_t)4 * ldb; }
            bptr += (size_t)16 * ldb;
        }
        __syncthreads();
#pragma unroll
        for (int ks = 0; ks < 2; ks++) {
            int kk = ks << 3;
            unsigned ah0 = __float_as_uint(sAh[arow_lo + kk + tig]);
            unsigned ah1 = __float_as_uint(sAh[arow_hi + kk + tig]);
            unsigned ah2 = __float_as_uint(sAh[arow_lo + kk + tig + 4]);
            unsigned ah3 = __float_as_uint(sAh[arow_hi + kk + tig + 4]);
            unsigned al0 = __float_as_uint(sAl[arow_lo + kk + tig]);
            unsigned al1 = __float_as_uint(sAl[arow_hi + kk + tig]);
            unsigned al2 = __float_as_uint(sAl[arow_lo + kk + tig + 4]);
            unsigned al3 = __float_as_uint(sAl[arow_hi + kk + tig + 4]);
            int bi0 = (kk + tig) * 72 + bcol;
            int bi1 = (kk + tig + 4) * 72 + bcol;
#pragma unroll
            for (int hlf = 0; hlf < 2; hlf++) {
                float bh0[4], bh1[4], bl0[4], bl1[4];
                *(float4*)bh0 = *(const float4*)&sBh[bi0 + (hlf << 2)];
                *(float4*)bh1 = *(const float4*)&sBh[bi1 + (hlf << 2)];
                *(float4*)bl0 = *(const float4*)&sBl[bi0 + (hlf << 2)];
                *(float4*)bl1 = *(const float4*)&sBl[bi1 + (hlf << 2)];
#pragma unroll
                for (int tt = 0; tt < 4; tt++) {
                    int t = (hlf << 2) + tt;
                    mma_tf32(acc[t], ah0, ah1, ah2, ah3,
                             __float_as_uint(bh0[tt]), __float_as_uint(bh1[tt]));
                    mma_tf32(acc[t], ah0, ah1, ah2, ah3,
                             __float_as_uint(bl0[tt]), __float_as_uint(bl1[tt]));
                    mma_tf32(acc[t], al0, al1, al2, al3,
                             __float_as_uint(bh0[tt]), __float_as_uint(bh1[tt]));
                }
            }
        }
    }

    int row0 = bm + r0 + g, row1 = row0 + 8;
#pragma unroll
    for (int t = 0; t < 8; t++) {
        int col = bn + (t << 3) + (tig << 1);
        if (col >= N) continue;
        float b0v = bias ? bias[col] : 0.f;
        float b1v = bias ? bias[col + 1] : 0.f;
        float v00 = acc[t][0] + b0v, v01 = acc[t][1] + b1v;
        float v10 = acc[t][2] + b0v, v11 = acc[t][3] + b1v;
        if (act) { v00 = silu_f(v00); v01 = silu_f(v01); v10 = silu_f(v10); v11 = silu_f(v11); }
        if (row0 < M) *(float2*)&C[(size_t)row0 * ldc + col] = make_float2(v00, v01);
        if (row1 < M) *(float2*)&C[(size_t)row1 * ldc + col] = make_float2(v10, v11);
    }
}

// ---------------- fused edge kernel v10: R15 + warp-local sync C ----------------
__global__ __launch_bounds__(256, 2) void k_edge2(
    const int* __restrict__ eidx, const float* __restrict__ coords,
    const float* __restrict__ b1,
    const float* __restrict__ b2,
    const float* __restrict__ eng, const float* __restrict__ enb) {
    extern __shared__ __align__(16) float sm[];
    float* s_fe = sm;
    float* s_H = sm;
    float* s_W0 = sm + 128 * 76;
    float* s_W1b = s_W0 + WCHUNK;
    float* s_b1 = s_W1b + WCHUNK;
    float* s_d2 = s_b1 + 648;
    int* s_src = (int*)(s_d2 + 128);
    int* s_dst = s_src + 128;

    int tid = threadIdx.x;
    int e0 = blockIdx.x << 7;

    unsigned w_smem0 = (unsigned)__cvta_generic_to_shared(s_W0);
    unsigned w_smem1 = (unsigned)__cvta_generic_to_shared(s_W1b);

    for (int idx = tid; idx < WCHUNK / 4; idx += 256) {
        asm volatile("cp.async.cg.shared.global [%0], [%1], 16;"
                     :: "r"(w_smem0 + (idx << 4)), "l"(g_We + (idx << 2)));
    }
    asm volatile("cp.async.commit_group;");

    if (tid < 128) {
        int e = e0 + tid;
        int s = eidx[e], d = eidx[NE + e];
        s_src[tid] = s; s_dst[tid] = d;
        float dx = coords[3 * s + 0] - coords[3 * d + 0];
        float dy = coords[3 * s + 1] - coords[3 * d + 1];
        float dz = coords[3 * s + 2] - coords[3 * d + 2];
        float d2 = dx * dx + dy * dy + dz * dz;
        s_d2[tid] = d2;
        s_fe[tid * 76 + 64] = to_tf32(d2);
#pragma unroll
        for (int j = 65; j < 72; j++) s_fe[tid * 76 + j] = 0.f;
    }
    for (int i = tid; i < 648; i += 256) s_b1[i] = (i < HID) ? b1[i] : 0.f;
    __syncthreads();
    for (int idx = tid; idx < 128 * 32; idx += 256) {
        int e = idx >> 5, i = idx & 31;
        float xs = s_d2[e] * __int_as_float((127 - i) << 23);
        float sv, cv;
        __sincosf(xs, &sv, &cv);
        s_fe[e * 76 + i] = to_tf32(sv);
        s_fe[e * 76 + 32 + i] = to_tf32(cv);
    }
    __syncthreads();

    int wid = tid >> 5, lane = tid & 31;
    int g = lane >> 2, tig = lane & 3;
    int r0 = wid << 4;
    int rlo = r0 + g, rhi = r0 + g + 8;

    unsigned feA[9][4];
#pragma unroll
    for (int ks = 0; ks < 9; ks++) {
        int k0 = ks << 3;
        feA[ks][0] = __float_as_uint(s_fe[rlo * 76 + k0 + tig]);
        feA[ks][1] = __float_as_uint(s_fe[rhi * 76 + k0 + tig]);
        feA[ks][2] = __float_as_uint(s_fe[rlo * 76 + k0 + tig + 4]);
        feA[ks][3] = __float_as_uint(s_fe[rhi * 76 + k0 + tig + 4]);
    }

    float acc[4][4];
#pragma unroll
    for (int t = 0; t < 4; t++)
#pragma unroll
        for (int u = 0; u < 4; u++) acc[t][u] = 0.f;

    for (int c = 0; c < 11; c++) {
        __syncthreads();  // A: prev chunk's GEMM2 done with s_H (cross-warp PQ writes follow)

        if (c < 10) {
            unsigned dst = ((c + 1) & 1) ? w_smem1 : w_smem0;
            const float* wsrc = g_We + (c + 1) * WCHUNK;
            for (int idx = tid; idx < WCHUNK / 4; idx += 256) {
                asm volatile("cp.async.cg.shared.global [%0], [%1], 16;"
                             :: "r"(dst + (idx << 4)), "l"(wsrc + (idx << 2)));
            }
            asm volatile("cp.async.commit_group;");
        }

        int cb = c << 6;
        for (int it = tid; it < 128 * 16; it += 256) {
            int e = it >> 4, q = it & 15;
            int col = cb + (q << 2);
            float4 r = make_float4(0.f, 0.f, 0.f, 0.f);
            if (col < HID) {
                float4 pa = *(const float4*)&g_Pa[(size_t)s_dst[e] * PLD + col];
                float4 pb = *(const float4*)&g_Pb[(size_t)s_src[e] * PLD + col];
                r.x = pa.x + pb.x + s_b1[col];
                r.y = (col + 1 < HID) ? pa.y + pb.y + s_b1[col + 1] : 0.f;
                r.z = (col + 2 < HID) ? pa.z + pb.z + s_b1[col + 2] : 0.f;
                r.w = (col + 3 < HID) ? pa.w + pb.w + s_b1[col + 3] : 0.f;
            }
            *(float4*)&s_H[e * 68 + (q << 2)] = r;
        }
        if (c < 10) {
            asm volatile("cp.async.wait_group 1;" ::: "memory");
        } else {
            asm volatile("cp.async.wait_group 0;" ::: "memory");
        }
        __syncthreads();  // B: PQ + weights visible

        float* s_Wc1 = (c & 1) ? s_W1b : s_W0;
        float* s_Wc2 = s_Wc1 + 72 * 72;

        float c1[8][4];
#pragma unroll
        for (int t = 0; t < 8; t++)
#pragma unroll
            for (int u = 0; u < 4; u++) c1[t][u] = 0.f;
#pragma unroll
        for (int ks = 0; ks < 9; ks++) {
            int k0 = ks << 3;
            int bi0 = (k0 + tig) * 72 + (g << 3);
            int bi1 = (k0 + tig + 4) * 72 + (g << 3);
#pragma unroll
            for (int half = 0; half < 2; half++) {
                float w0[4], w1[4];
                *(float4*)w0 = *(const float4*)&s_Wc1[bi0 + (half << 2)];
                *(float4*)w1 = *(const float4*)&s_Wc1[bi1 + (half << 2)];
#pragma unroll
                for (int tt = 0; tt < 4; tt++) {
                    mma_tf32(c1[(half << 2) + tt], feA[ks][0], feA[ks][1], feA[ks][2], feA[ks][3],
                             __float_as_uint(w0[tt]), __float_as_uint(w1[tt]));
                }
            }
        }
        // epilogue: H rows r0..r0+15 are warp-owned (written and then read by GEMM2
        // within the same warp) -> warp-level sync suffices.
#pragma unroll
        for (int t = 0; t < 8; t++) {
            int col = (t << 3) + (tig << 1);
            int i00 = rlo * 68 + col;
            int i10 = rhi * 68 + col;
            s_H[i00] = to_tf32(silu_f(c1[t][0] + s_H[i00]));
            s_H[i00 + 1] = to_tf32(silu_f(c1[t][1] + s_H[i00 + 1]));
            s_H[i10] = to_tf32(silu_f(c1[t][2] + s_H[i10]));
            s_H[i10 + 1] = to_tf32(silu_f(c1[t][3] + s_H[i10 + 1]));
        }
        __syncwarp();  // C (warp-local): epilogue writes visible to this warp's GEMM2 reads

        // GEMM2: acc += H @ W2c (reads only this warp's 16 rows of s_H)
#pragma unroll
        for (int ks = 0; ks < 8; ks++) {
            int k0 = ks << 3;
            unsigned a0 = __float_as_uint(s_H[rlo * 68 + k0 + tig]);
            unsigned a1 = __float_as_uint(s_H[rhi * 68 + k0 + tig]);
            unsigned a2 = __float_as_uint(s_H[rlo * 68 + k0 + tig + 4]);
            unsigned a3 = __float_as_uint(s_H[rhi * 68 + k0 + tig + 4]);
            float w0[4], w1[4];
            *(float4*)w0 = *(const float4*)&s_Wc2[(k0 + tig) * 40 + (g << 2)];
            *(float4*)w1 = *(const float4*)&s_Wc2[(k0 + tig + 4) * 40 + (g << 2)];
#pragma unroll
            for (int t = 0; t < 4; t++) {
                mma_tf32(acc[t], a0, a1, a2, a3,
                         __float_as_uint(w0[t]), __float_as_uint(w1[t]));
            }
        }
    }

    int dlo = s_dst[rlo], dhi = s_dst[rhi];
    float vlo[8], vhi[8];
    float Slo = 0.f, Shi = 0.f;
#pragma unroll
    for (int t = 0; t < 4; t++) {
        int col = (t << 3) + (tig << 1);
        float v0 = silu_f(acc[t][0] + b2[col]);
        float v1 = silu_f(acc[t][1] + b2[col + 1]);
        float v2 = silu_f(acc[t][2] + b2[col]);
        float v3 = silu_f(acc[t][3] + b2[col + 1]);
        vlo[t * 2] = v0; vlo[t * 2 + 1] = v1;
        vhi[t * 2] = v2; vhi[t * 2 + 1] = v3;
        Slo += v0 + v1; Shi += v2 + v3;
    }
    Slo += __shfl_xor_sync(0xffffffffu, Slo, 1);
    Slo += __shfl_xor_sync(0xffffffffu, Slo, 2);
    Shi += __shfl_xor_sync(0xffffffffu, Shi, 1);
    Shi += __shfl_xor_sync(0xffffffffu, Shi, 2);
    float mlo = Slo * (1.f / 32.f), mhi = Shi * (1.f / 32.f);
    float Vlo = 0.f, Vhi = 0.f;
#pragma unroll
    for (int u = 0; u < 8; u++) {
        float d0 = vlo[u] - mlo; Vlo += d0 * d0;
        float d1 = vhi[u] - mhi; Vhi += d1 * d1;
    }
    Vlo += __shfl_xor_sync(0xffffffffu, Vlo, 1);
    Vlo += __shfl_xor_sync(0xffffffffu, Vlo, 2);
    Vhi += __shfl_xor_sync(0xffffffffu, Vhi, 1);
    Vhi += __shfl_xor_sync(0xffffffffu, Vhi, 2);
    float ilo = rsqrtf(Vlo * (1.f / 32.f) + EPSF);
    float ihi = rsqrtf(Vhi * (1.f / 32.f) + EPSF);
#pragma unroll
    for (int t = 0; t < 4; t++) {
#pragma unroll
        for (int d = 0; d < 2; d++) {
            int col = (t << 3) + (tig << 1) + d;
            atomicAdd(&g_seg[dlo * MD + col], (vlo[t * 2 + d] - mlo) * ilo * eng[col] + enb[col]);
            atomicAdd(&g_seg[dhi * MD + col], (vhi[t * 2 + d] - mhi) * ihi * eng[col] + enb[col]);
        }
    }
}

// ---------------- node pre ----------------
__global__ void k_node_pre(int off, const float* __restrict__ eng, const float* __restrict__ enb,
                           const float* __restrict__ n1g, const float* __restrict__ n1b) {
    int node = blockIdx.x * 8 + (threadIdx.x >> 5);
    int lane = threadIdx.x & 31;
    if (node >= NN) return;

    float x = g_seg[node * MD + lane] / fmaxf(g_cnt[node], 1.f);
    g_seg[node * MD + lane] = 0.f;
    float S = x;
#pragma unroll
    for (int o = 16; o; o >>= 1) S += __shfl_xor_sync(0xffffffffu, S, o);
    float mean = S * (1.f / 32.f);
    float d = x - mean;
    float V = d * d;
#pragma unroll
    for (int o = 16; o; o >>= 1) V += __shfl_xor_sync(0xffffffffu, V, o);
    V *= (1.f / 32.f);
    g_z[node * 160 + 128 + lane] = d * rsqrtf(V + EPSF) * eng[lane] + enb[lane];

    float4 v = *(const float4*)&g_cat[node * CAT + off + lane * 4];
    S = v.x + v.y + v.z + v.w;
#pragma unroll
    for (int o = 16; o; o >>= 1) S += __shfl_xor_sync(0xffffffffu, S, o);
    mean = S * (1.f / 128.f);
    float dx = v.x - mean, dy = v.y - mean, dz = v.z - mean, dw = v.w - mean;
    V = dx * dx + dy * dy + dz * dz + dw * dw;
#pragma unroll
    for (int o = 16; o; o >>= 1) V += __shfl_xor_sync(0xffffffffu, V, o);
    V *= (1.f / 128.f);
    float inv = rsqrtf(V + EPSF);
    float4 g4 = *(const float4*)&n1g[lane * 4];
    float4 b4 = *(const float4*)&n1b[lane * 4];
    float4 o4;
    o4.x = dx * inv * g4.x + b4.x;
    o4.y = dy * inv * g4.y + b4.y;
    o4.z = dz * inv * g4.z + b4.z;
    o4.w = dw * inv * g4.w + b4.w;
    *(float4*)&g_z[node * 160 + lane * 4] = o4;
}

// ---------------- node post ----------------
__global__ void k_node_post(int off, const float* __restrict__ n2g, const float* __restrict__ n2b) {
    int node = blockIdx.x * 8 + (threadIdx.x >> 5);
    int lane = threadIdx.x & 31;
    if (node >= NN) return;
    float4 v = *(const float4*)&g_h2[node * 128 + lane * 4];
    float S = v.x + v.y + v.z + v.w;
#pragma unroll
    for (int o = 16; o; o >>= 1) S += __shfl_xor_sync(0xffffffffu, S, o);
    float mean = S * (1.f / 128.f);
    float dx = v.x - mean, dy = v.y - mean, dz = v.z - mean, dw = v.w - mean;
    float V = dx * dx + dy * dy + dz * dz + dw * dw;
#pragma unroll
    for (int o = 16; o; o >>= 1) V += __shfl_xor_sync(0xffffffffu, V, o);
    V *= (1.f / 128.f);
    float inv = rsqrtf(V + EPSF);
    float4 g4 = *(const float4*)&n2g[lane * 4];
    float4 b4 = *(const float4*)&n2b[lane * 4];
    float4 old = *(const float4*)&g_cat[node * CAT + off + lane * 4];
    float4 o4;
    o4.x = old.x + dx * inv * g4.x + b4.x;
    o4.y = old.y + dy * inv * g4.y + b4.y;
    o4.z = old.z + dz * inv * g4.z + b4.z;
    o4.w = old.w + dw * inv * g4.w + b4.w;
    *(float4*)&g_cat[node * CAT + off + 128 + lane * 4] = o4;
    int base = node * EMB + lane * 4;
    float h;
    h = to_tf32(o4.x); g_Ah[base + 0] = h; g_Al[base + 0] = to_tf32(o4.x - h);
    h = to_tf32(o4.y); g_Ah[base + 1] = h; g_Al[base + 1] = to_tf32(o4.y - h);
    h = to_tf32(o4.z); g_Ah[base + 2] = h; g_Al[base + 2] = to_tf32(o4.z - h);
    h = to_tf32(o4.w); g_Ah[base + 3] = h; g_Al[base + 3] = to_tf32(o4.w - h);
}

// ---------------- graph head ----------------
__global__ void k_graph(const float* __restrict__ g1W, const float* __restrict__ g1b,
                        const float* __restrict__ g2W, const float* __restrict__ g2b,
                        const float* __restrict__ g3W, const float* __restrict__ g3b,
                        float* __restrict__ out) {
    __shared__ float h[256], t[256];
    int g = blockIdx.x, tid = threadIdx.x;
    float c = fmaxf(g_pcnt[g], 1.f);
    h[tid] = g_pool[g * 256 + tid] / c;
    __syncthreads();
    float a = g1b[tid];
    for (int k = 0; k < 256; k++) a += h[k] * g1W[k * 256 + tid];
    t[tid] = silu_f(a);
    __syncthreads();
    h[tid] = t[tid];
    __syncthreads();
    a = g2b[tid];
    for (int k = 0; k < 256; k++) a += h[k] * g2W[k * 256 + tid];
    t[tid] = silu_f(a);
    __syncthreads();
    h[tid] = t[tid];
    __syncthreads();
    t[tid] = h[tid] * g3W[tid];
    __syncthreads();
    for (int s = 128; s; s >>= 1) {
        if (tid < s) t[tid] += t[tid + s];
        __syncthreads();
    }
    if (tid == 0) out[g] = t[0] + g3b[0];
}

// ---------------- launch ----------------
extern "C" void kernel_launch(void* const* d_in, const int* in_sizes, int n_in,
                              void* d_out, int out_size) {
    const int* atomids = (const int*)d_in[0];
    const float* coords = (const float*)d_in[1];
    const int* eidx = (const int*)d_in[2];
    const int* batch = (const int*)d_in[3];
    const float* emb_w = (const float*)d_in[4];
    const float* eW1 = (const float*)d_in[5];
    const float* eb1 = (const float*)d_in[6];
    const float* eW2 = (const float*)d_in[7];
    const float* eb2 = (const float*)d_in[8];
    const float* en_g = (const float*)d_in[9];
    const float* en_b = (const float*)d_in[10];
    const float* nn1_g = (const float*)d_in[11];
    const float* nn1_b = (const float*)d_in[12];
    const float* nW1 = (const float*)d_in[13];
    const float* nb1 = (const float*)d_in[14];
    const float* nW2 = (const float*)d_in[15];
    const float* nb2 = (const float*)d_in[16];
    const float* nn2_g = (const float*)d_in[17];
    const float* nn2_b = (const float*)d_in[18];
    const float* f1W = (const float*)d_in[19];
    const float* f1b = (const float*)d_in[20];
    const float* f2W = (const float*)d_in[21];
    const float* f2b = (const float*)d_in[22];
    const float* f3W = (const float*)d_in[23];
    const float* f3b = (const float*)d_in[24];
    const float* g1W = (const float*)d_in[25];
    const float* g1b = (const float*)d_in[26];
    const float* g2W = (const float*)d_in[27];
    const float* g2b = (const float*)d_in[28];
    const float* g3W = (const float*)d_in[29];
    const float* g3b = (const float*)d_in[30];
    float* out = (float*)d_out;

    const int smem_edge = (128 * 76 + 2 * WCHUNK + 648 + 128 + 256) * 4;  // 104992 B
    cudaFuncSetAttribute(k_edge2, cudaFuncAttributeMaxDynamicSharedMemorySize, smem_edge);

    float *pcat, *pPa, *pPb, *pAh, *pAl, *pWh, *pWl, *pz, *ph1, *ph2, *pf1, *pf2, *pf3;
    cudaGetSymbolAddress((void**)&pcat, g_cat);
    cudaGetSymbolAddress((void**)&pPa, g_Pa);
    cudaGetSymbolAddress((void**)&pPb, g_Pb);
    cudaGetSymbolAddress((void**)&pAh, g_Ah);
    cudaGetSymbolAddress((void**)&pAl, g_Al);
    cudaGetSymbolAddress((void**)&pWh, g_Wh);
    cudaGetSymbolAddress((void**)&pWl, g_Wl);
    cudaGetSymbolAddress((void**)&pz, g_z);
    cudaGetSymbolAddress((void**)&ph1, g_h1);
    cudaGetSymbolAddress((void**)&ph2, g_h2);
    cudaGetSymbolAddress((void**)&pf1, g_f1);
    cudaGetSymbolAddress((void**)&pf2, g_f2);
    cudaGetSymbolAddress((void**)&pf3, g_f3);

    k_zero_start<<<(NN * MD + 255) / 256, 256>>>();
    k_deg<<<(NE + 255) / 256, 256>>>(eidx);
    k_embed<<<(NN * EMB + 255) / 256, 256>>>(atomids, emb_w);

    const int MB = (NN + 127) / 128;  // 79

    for (int k = 0; k < 5; k++) {
        int off = 128 * k;
        k_split_w<<<(256 * HID + 255) / 256, 256>>>(eW1 + (size_t)k * EIN * HID);
        k_prep_we<<<(11 * WCHUNK + 255) / 256, 256>>>(eW1 + (size_t)k * EIN * HID,
                                                      eW2 + (size_t)k * HID * MD);
        k_gemm3p<<<dim3(22, MB), 256>>>(pAh, pAl, pWh, pWl, pPa, pPb);
        k_edge2<<<NE / 128, 256, smem_edge>>>(eidx, coords, eb1 + k * HID, eb2 + k * MD,
                                              en_g + k * MD, en_b + k * MD);
        k_node_pre<<<NN / 8, 256>>>(off, en_g + k * MD, en_b + k * MD,
                                    nn1_g + k * EMB, nn1_b + k * EMB);
        k_gemm3t<<<dim3(4, MB), 256>>>(pz, nW1 + (size_t)k * 160 * 256, nb1 + k * 256, ph1,
                                       NN, 256, 160, 160, 256, 256, 1, 0);
        k_gemm3t<<<dim3(2, MB), 256>>>(ph1, nW2 + (size_t)k * 256 * 128, nb2 + k * 128, ph2,
                                       NN, 128, 256, 256, 128, 128, 0, 0);
        k_node_post<<<NN / 8, 256>>>(off, nn2_g + k * EMB, nn2_b + k * EMB);
    }

    k_gemm3t<<<dim3(4, MB), 256>>>(pcat, f1W, f1b, pf1, NN, 256, CAT, CAT, 256, 256, 1, 1);
    k_gemm3t<<<dim3(4, MB), 256>>>(pf1, f2W, f2b, pf2, NN, 256, 256, 256, 256, 256, 1, 0);
    k_gemm3t<<<dim3(4, MB), 256>>>(pf2, f3W, f3b, pf3, NN, 256, 256, 256, 256, 256, 1, 0);
    k_pool<<<(NN * 256 + 255) / 256, 256>>>(batch);
    k_graph<<<NG, 256>>>(g1W, g1b, g2W, g2b, g3W, g3b, out);
}